// round 16
// baseline (speedup 1.0000x reference)
#include <cuda_runtime.h>
#include <cuda_fp16.h>
#include <stdint.h>
#include <float.h>
#include <math.h>

// ---------------- problem constants ----------------
#define B_    4
#define T_    32768
#define BT    (B_ * T_)          // 131072 points
#define RESO_ 128
#define R2_   (RESO_ * RESO_)    // 16384
#define NSEG  (B_ * R2_)         // 65536 segments
#define H     128
#define H2    256
#define CDIM  64
#define NB    5

// per-block converted-weight region (halves): w0 (32768) | ws (32768) | w1 (16384)
#define WBLK  81920
#define FCW_OFF (NB * WBLK)      // fc_c weight, tiled fp16 [8 tiles][64][16] = 8192

// ---------------- scratch (device globals, no allocation) ----------------
__device__ int    g_idx[3][BT];
__device__ int    g_rank[3][BT];
__device__ int    g_bcnt[3][NSEG];
__device__ int    g_boff[3][NSEG];        // chunk-local exclusive offsets
__device__ int    g_bsum[3][32];          // exclusive chunk base offsets
__device__ int    g_pts[3][BT];
__device__ __align__(16) __half g_net[(size_t)BT * H];
__device__ __align__(16) __half g_segmax[3][(size_t)NSEG * H];
__device__ __align__(16) __half g_wcvt[NB * WBLK + 8192];
__device__ float  g_c[(size_t)BT * CDIM];

// ---------------- helpers ----------------
__device__ __forceinline__ int norm_bin(float v) {
    float u = v / 1.10001f + 0.5f;
    u = fminf(fmaxf(u, 0.0f), 0.99999f);
    int q = (int)(u * 128.0f);
    return q < 127 ? q : 127;
}

__device__ __forceinline__ uint32_t smem_u32(const void* p) {
    uint32_t a;
    asm("{ .reg .u64 t; cvta.to.shared.u64 t, %1; cvt.u32.u64 %0, t; }"
        : "=r"(a) : "l"(p));
    return a;
}

#define LDSM_X4(r0, r1, r2, r3, addr) \
    asm volatile("ldmatrix.sync.aligned.m8n8.x4.shared.b16 {%0,%1,%2,%3}, [%4];" \
        : "=r"(r0), "=r"(r1), "=r"(r2), "=r"(r3) : "r"(addr))

#define CP_ASYNC16(dst_sh, src_g) \
    asm volatile("cp.async.cg.shared.global [%0], [%1], 16;" \
        :: "r"(dst_sh), "l"(src_g) : "memory")
#define CP_COMMIT() asm volatile("cp.async.commit_group;" ::: "memory")
#define CP_WAIT0()  asm volatile("cp.async.wait_group 0;" ::: "memory")

// ---------------- weight convert (+ bcnt zero) ----------------
// W[K][128] fp32 -> fp16 tiled: elem (k,n) at ((k>>4)*128 + n)*16 + (k&15)
// fcw[K=128][64] -> tiled ((k>>4)*64 + n)*16 + (k&15) at FCW_OFF
__global__ void k_cvtw(const float* __restrict__ w0,
                       const float* __restrict__ ws,
                       const float* __restrict__ w1,
                       const float* __restrict__ fcw) {
    int t = blockIdx.x * 256 + threadIdx.x;        // 0 .. NB*WBLK+8192-1
    if (t < 3 * NSEG) (&g_bcnt[0][0])[t] = 0;      // fused zeroing
    if (t >= NB * WBLK) {
        int r = t - NB * WBLK;                     // < 8192
        int k = r >> 6, n = r & 63;
        g_wcvt[FCW_OFF + ((k >> 4) * 64 + n) * 16 + (k & 15)] =
            __float2half(fcw[r]);
        return;
    }
    int blk = t / WBLK;
    int r = t - blk * WBLK;
    const float* src;
    int base;
    if (r < 32768)      { src = w0 + (size_t)blk * 32768 + r;           base = 0;     }
    else if (r < 65536) { src = ws + (size_t)blk * 32768 + (r - 32768); base = 32768; r -= 32768; }
    else                { src = w1 + (size_t)blk * 16384 + (r - 65536); base = 65536; r -= 65536; }
    int k = r >> 7, n = r & 127;
    g_wcvt[(size_t)blk * WBLK + base + ((k >> 4) * 128 + n) * 16 + (k & 15)] =
        __float2half(*src);
}

// ---------------- index / CSR build ----------------
__global__ void k_idxcount(const float* __restrict__ p) {
    int i = blockIdx.x * 256 + threadIdx.x;
    if (i >= BT) return;
    float x = p[3 * i + 0], y = p[3 * i + 1], z = p[3 * i + 2];
    int base = (i / T_) * R2_;
    int ix = norm_bin(x), iy = norm_bin(y), iz = norm_bin(z);
    int idx0 = base + ix + RESO_ * iz;
    int idx1 = base + ix + RESO_ * iy;
    int idx2 = base + iy + RESO_ * iz;
    g_idx[0][i] = idx0; g_idx[1][i] = idx1; g_idx[2][i] = idx2;
    g_rank[0][i] = atomicAdd(&g_bcnt[0][idx0], 1);
    g_rank[1][i] = atomicAdd(&g_bcnt[1][idx1], 1);
    g_rank[2][i] = atomicAdd(&g_bcnt[2][idx2], 1);
}

__global__ void k_scanA() {       // 2048-elem chunks, 32 chunks/plane
    int pl = blockIdx.y, chunk = blockIdx.x;
    int tid = threadIdx.x;
    int base = chunk * 2048 + tid * 2;
    int v0 = g_bcnt[pl][base], v1 = g_bcnt[pl][base + 1];
    int v = v0 + v1;
    int lane = tid & 31, wid = tid >> 5;
    int x = v;
#pragma unroll
    for (int o = 1; o < 32; o <<= 1) {
        int y = __shfl_up_sync(0xffffffffu, x, o);
        if (lane >= o) x += y;
    }
    __shared__ int wsum[32];
    if (lane == 31) wsum[wid] = x;
    __syncthreads();
    if (wid == 0) {
        int s = wsum[lane];
#pragma unroll
        for (int o = 1; o < 32; o <<= 1) {
            int y = __shfl_up_sync(0xffffffffu, s, o);
            if (lane >= o) s += y;
        }
        wsum[lane] = s;
    }
    __syncthreads();
    int incl = x + (wid ? wsum[wid - 1] : 0);
    int excl = incl - v;
    g_boff[pl][base] = excl;
    g_boff[pl][base + 1] = excl + v0;
    if (tid == 1023) g_bsum[pl][chunk] = incl;
}

__global__ void k_scanB() {       // 1 block, 96 threads: warp per plane
    int pl = threadIdx.x >> 5, lane = threadIdx.x & 31;
    int v = g_bsum[pl][lane];
    int x = v;
#pragma unroll
    for (int o = 1; o < 32; o <<= 1) {
        int y = __shfl_up_sync(0xffffffffu, x, o);
        if (lane >= o) x += y;
    }
    g_bsum[pl][lane] = x - v;     // exclusive chunk base
}

__global__ void k_scatter() {
    int i = blockIdx.x * 256 + threadIdx.x;   // BT
#pragma unroll
    for (int pl = 0; pl < 3; pl++) {
        int bin = g_idx[pl][i];
        int off = g_boff[pl][bin] + g_bsum[pl][bin >> 11];
        g_pts[pl][off + g_rank[pl][i]] = i;
    }
}

// ---------------- fused resblock (fp16 MMA + ldmatrix + cp.async) ---------
// MODE 0: X = fc_pos(p) inline.  MODE 1: X = [net | sum3 segmax(idx)] inline.
// NET = X@ws + relu(relu(X)@w0 + b0)@w1 + b1;  FC 1: also C = net@fcw + fcb.
// BM=64, 256 thr (wm 2 x wn 4), warp tile 32x32, 2 CTAs/SM.
// 4-deep buffer rings, 2 k-tiles per __syncthreads, cp.async B staging.
// smem (halves):
//   AS  [4][64][24]   @0
//   B0  [4][128][24]  @6144
//   BS  [4][128][24]  @18432
//   HS  [64][136]     @30720
#define RB_ASR 24
#define RB_BSR 24
#define RB_HSR 136
#define OFF_B0 6144
#define OFF_BS 18432
#define OFF_HS 30720
#define RB_SMEM_BYTES ((30720 + 64 * RB_HSR) * 2)   // 78848 B

#define MMA_F16(d, a, b) \
    asm volatile( \
        "mma.sync.aligned.m16n8k16.row.col.f32.f16.f16.f32 " \
        "{%0,%1,%2,%3}, {%4,%5,%6,%7}, {%8,%9}, {%0,%1,%2,%3};" \
        : "+f"((d)[0]), "+f"((d)[1]), "+f"((d)[2]), "+f"((d)[3]) \
        : "r"((a)[0]), "r"((a)[1]), "r"((a)[2]), "r"((a)[3]), \
          "r"((b)[0]), "r"((b)[1]))

template <int MODE, int FC>
__global__ void __launch_bounds__(256, 2)
k_resblock(const float* __restrict__ P,      // MODE 0: [BT,3]
           const float* __restrict__ FW,     // MODE 0: [3,256]
           const float* __restrict__ FB,     // MODE 0: [256]
           const __half* __restrict__ w0h,   // tiled fp16 [16 tiles][128][16]
           const float* __restrict__ b0,
           const __half* __restrict__ w1h,   // tiled fp16 [8 tiles][128][16]
           const float* __restrict__ b1,
           const __half* __restrict__ wsh,   // tiled fp16 [16 tiles][128][16]
           __half* __restrict__ NET,         // [BT,128] fp16 (in-place safe)
           const __half* __restrict__ fcw16, // FC: tiled fp16 [8 tiles][64][16]
           const float* __restrict__ fcb,    // FC: [64]
           float* __restrict__ Cout) {       // FC: [BT,64]
    extern __shared__ __half hsm[];
    uint32_t sbh = smem_u32(hsm);
    int tid = threadIdx.x;
    int bm = blockIdx.x * 64;
    int w = tid >> 5, lane = tid & 31;
    int wm = w & 1, wn = w >> 1;              // 2 x 4
    int lr = lane >> 2, lc = lane & 3;
    int jrow = lane & 7, jsel = lane >> 3;    // ldmatrix lane mapping

    int arow = tid >> 2;            // 0..63
    int acol = (tid & 3) * 4;       // 0,4,8,12
    int bn = tid & 127;             // n for B staging
    int bkh = (tid >> 7) * 8;       // k-half offset (0 or 8)

    // per-row state for A synthesis
    int row = bm + arow;
    float p0, p1, p2;
    int ix0, ix1, ix2;
    if (MODE == 0) {
        p0 = P[3 * row]; p1 = P[3 * row + 1]; p2 = P[3 * row + 2];
    } else {
        ix0 = g_idx[0][row]; ix1 = g_idx[1][row]; ix2 = g_idx[2][row];
    }

    float accH[2][4][4];
    float accS[2][4][4];
#pragma unroll
    for (int mi = 0; mi < 2; mi++)
#pragma unroll
        for (int ni = 0; ni < 4; ni++)
#pragma unroll
            for (int q = 0; q < 4; q++) { accH[mi][ni][q] = 0.f; accS[mi][ni][q] = 0.f; }

    uint2 ap[2];

    auto loadA = [&](int k0) -> uint2 {
        int col = k0 + acol;
        if (MODE == 0) {
            float4 wa = *(const float4*)&FW[col];
            float4 wb = *(const float4*)&FW[H2 + col];
            float4 wc = *(const float4*)&FW[2 * H2 + col];
            float4 bb = *(const float4*)&FB[col];
            __half2 h0 = __floats2half2_rn(p0 * wa.x + p1 * wb.x + p2 * wc.x + bb.x,
                                           p0 * wa.y + p1 * wb.y + p2 * wc.y + bb.y);
            __half2 h1 = __floats2half2_rn(p0 * wa.z + p1 * wb.z + p2 * wc.z + bb.z,
                                           p0 * wa.w + p1 * wb.w + p2 * wc.w + bb.w);
            uint2 r; r.x = *(unsigned*)&h0; r.y = *(unsigned*)&h1;
            return r;
        } else {
            if (col < H) {   // uniform per k-tile
                return *(const uint2*)&g_net[(size_t)row * H + col];
            } else {
                int c2 = col - H;
                uint2 ua = *(const uint2*)&g_segmax[0][(size_t)ix0 * H + c2];
                uint2 ub = *(const uint2*)&g_segmax[1][(size_t)ix1 * H + c2];
                uint2 uc = *(const uint2*)&g_segmax[2][(size_t)ix2 * H + c2];
                float2 a0 = __half22float2(*(__half2*)&ua.x), a1 = __half22float2(*(__half2*)&ua.y);
                float2 e0 = __half22float2(*(__half2*)&ub.x), e1 = __half22float2(*(__half2*)&ub.y);
                float2 c0 = __half22float2(*(__half2*)&uc.x), c1 = __half22float2(*(__half2*)&uc.y);
                __half2 h0 = __floats2half2_rn(a0.x + e0.x + c0.x, a0.y + e0.y + c0.y);
                __half2 h1 = __floats2half2_rn(a1.x + e1.x + c1.x, a1.y + e1.y + c1.y);
                uint2 r; r.x = *(unsigned*)&h0; r.y = *(unsigned*)&h1;
                return r;
            }
        }
    };

    auto stA = [&](int buf, uint2 v) {
        *(uint2*)&hsm[buf * (64 * RB_ASR) + arow * RB_ASR + acol] = v;
    };
    auto cpB = [&](int offb, int buf, const __half* W16, int kt) {
        unsigned dst = sbh + (offb + buf * (128 * RB_BSR) + bn * RB_BSR + bkh) * 2;
        CP_ASYNC16(dst, &W16[((size_t)kt * 128 + bn) * 16 + bkh]);
    };

    __half2 zero2 = __floats2half2_rn(0.f, 0.f);
    unsigned zu = *(unsigned*)&zero2;

    unsigned aAddrBase = ((wm * 32 + (jsel & 1) * 8 + jrow) * RB_ASR + (jsel >> 1) * 8) * 2;
    unsigned bAddrBase = ((wn * 32 + (jsel >> 1) * 8 + jrow) * RB_BSR + (jsel & 1) * 8) * 2;
    unsigned hAddrBase = ((wm * 32 + (jsel & 1) * 8 + jrow) * RB_HSR + (jsel >> 1) * 8) * 2;

    // ---- phase 1: K=256, accH = relu(X)@w0, accS = X@ws ----
    ap[0] = loadA(0);
    ap[1] = loadA(16);
    cpB(OFF_B0, 0, w0h, 0); cpB(OFF_B0, 1, w0h, 1);
    cpB(OFF_BS, 0, wsh, 0); cpB(OFF_BS, 1, wsh, 1);
    CP_COMMIT();
    stA(0, ap[0]); stA(1, ap[1]);
    CP_WAIT0();
    __syncthreads();

    for (int s = 0; s < 16; s += 2) {
        if (s + 2 < 16) {
            cpB(OFF_B0, (s + 2) & 3, w0h, s + 2); cpB(OFF_BS, (s + 2) & 3, wsh, s + 2);
            cpB(OFF_B0, (s + 3) & 3, w0h, s + 3); cpB(OFF_BS, (s + 3) & 3, wsh, s + 3);
            CP_COMMIT();
            ap[0] = loadA((s + 2) * 16);
            ap[1] = loadA((s + 3) * 16);
        }
#pragma unroll
        for (int u = 0; u < 2; u++) {
            int cur = (s + u) & 3;
            unsigned afr[2][4], afh[2][4], bf0[4][2], bfs[4][2];
            unsigned aA = sbh + cur * (64 * RB_ASR) * 2 + aAddrBase;
            unsigned bA = sbh + (OFF_B0 + cur * (128 * RB_BSR)) * 2 + bAddrBase;
            unsigned sA = sbh + (OFF_BS + cur * (128 * RB_BSR)) * 2 + bAddrBase;
#pragma unroll
            for (int mi = 0; mi < 2; mi++) {
                LDSM_X4(afr[mi][0], afr[mi][1], afr[mi][2], afr[mi][3],
                        aA + mi * (16 * RB_ASR) * 2);
#pragma unroll
                for (int q = 0; q < 4; q++) {
                    __half2 hh = __hmax2(*(__half2*)&afr[mi][q], *(__half2*)&zu);
                    afh[mi][q] = *(unsigned*)&hh;
                }
            }
            LDSM_X4(bf0[0][0], bf0[0][1], bf0[1][0], bf0[1][1], bA);
            LDSM_X4(bf0[2][0], bf0[2][1], bf0[3][0], bf0[3][1], bA + (16 * RB_BSR) * 2);
            LDSM_X4(bfs[0][0], bfs[0][1], bfs[1][0], bfs[1][1], sA);
            LDSM_X4(bfs[2][0], bfs[2][1], bfs[3][0], bfs[3][1], sA + (16 * RB_BSR) * 2);
#pragma unroll
            for (int mi = 0; mi < 2; mi++)
#pragma unroll
                for (int ni = 0; ni < 4; ni++) {
                    MMA_F16(accH[mi][ni], afh[mi], bf0[ni]);
                    MMA_F16(accS[mi][ni], afr[mi], bfs[ni]);
                }
        }
        if (s + 2 < 16) {
            stA((s + 2) & 3, ap[0]);
            stA((s + 3) & 3, ap[1]);
            CP_WAIT0();
        }
        __syncthreads();
    }

    // ---- w1 prefetch (B0 bufs 0,1 are dead) + store HS = relu(accH+b0) ----
    cpB(OFF_B0, 0, w1h, 0);
    cpB(OFF_B0, 1, w1h, 1);
    CP_COMMIT();
#pragma unroll
    for (int mi = 0; mi < 2; mi++)
#pragma unroll
        for (int ni = 0; ni < 4; ni++) {
            int n = wn * 32 + ni * 8 + lc * 2;
            float bv0 = b0[n], bv1 = b0[n + 1];
#pragma unroll
            for (int half = 0; half < 2; half++) {
                int m = wm * 32 + mi * 16 + lr + half * 8;
                __half2 hv = __floats2half2_rn(
                    fmaxf(accH[mi][ni][half * 2 + 0] + bv0, 0.f),
                    fmaxf(accH[mi][ni][half * 2 + 1] + bv1, 0.f));
                *(__half2*)&hsm[OFF_HS + m * RB_HSR + n] = hv;
            }
        }
    CP_WAIT0();
    __syncthreads();

    // ---- phase 2: accS += relu(hidden) @ w1, K=128 ----
    for (int s = 0; s < 8; s += 2) {
        if (s + 2 < 8) {
            cpB(OFF_B0, (s + 2) & 3, w1h, s + 2);
            cpB(OFF_B0, (s + 3) & 3, w1h, s + 3);
            CP_COMMIT();
        }
#pragma unroll
        for (int u = 0; u < 2; u++) {
            int kt = s + u, cur = kt & 3;
            unsigned af[2][4], bf[4][2];
            unsigned hA = sbh + OFF_HS * 2 + hAddrBase + kt * 16 * 2;
            unsigned bA = sbh + (OFF_B0 + cur * (128 * RB_BSR)) * 2 + bAddrBase;
#pragma unroll
            for (int mi = 0; mi < 2; mi++)
                LDSM_X4(af[mi][0], af[mi][1], af[mi][2], af[mi][3],
                        hA + mi * (16 * RB_HSR) * 2);
            LDSM_X4(bf[0][0], bf[0][1], bf[1][0], bf[1][1], bA);
            LDSM_X4(bf[2][0], bf[2][1], bf[3][0], bf[3][1], bA + (16 * RB_BSR) * 2);
#pragma unroll
            for (int mi = 0; mi < 2; mi++)
#pragma unroll
                for (int ni = 0; ni < 4; ni++)
                    MMA_F16(accS[mi][ni], af[mi], bf[ni]);
        }
        if (s + 2 < 8) CP_WAIT0();
        __syncthreads();
    }

    // ---- epilogue: net = accS + b1 ----
    if (!FC) {
#pragma unroll
        for (int mi = 0; mi < 2; mi++)
#pragma unroll
            for (int ni = 0; ni < 4; ni++) {
                int n = wn * 32 + ni * 8 + lc * 2;
                float bv0 = b1[n], bv1 = b1[n + 1];
#pragma unroll
                for (int half = 0; half < 2; half++) {
                    int m = bm + wm * 32 + mi * 16 + lr + half * 8;
                    *(__half2*)&NET[(size_t)m * H + n] =
                        __floats2half2_rn(accS[mi][ni][half * 2 + 0] + bv0,
                                          accS[mi][ni][half * 2 + 1] + bv1);
                }
            }
        return;
    }

    // ---- FC path: net -> HS (fp16), then C = net@fcw + fcb ----
#pragma unroll
    for (int mi = 0; mi < 2; mi++)
#pragma unroll
        for (int ni = 0; ni < 4; ni++) {
            int n = wn * 32 + ni * 8 + lc * 2;
            float bv0 = b1[n], bv1 = b1[n + 1];
#pragma unroll
            for (int half = 0; half < 2; half++) {
                int m = wm * 32 + mi * 16 + lr + half * 8;
                *(__half2*)&hsm[OFF_HS + m * RB_HSR + n] =
                    __floats2half2_rn(accS[mi][ni][half * 2 + 0] + bv0,
                                      accS[mi][ni][half * 2 + 1] + bv1);
            }
        }
    int fn = tid & 63, fkh = ((tid >> 6) & 1) * 8;
    uint4 fv;
    if (tid < 128) {
        fv = *(const uint4*)&fcw16[(0 * 64 + fn) * 16 + fkh];
    }
    __syncthreads();   // HS(net) visible; phase-2 B0 dead
    if (tid < 128)
        *(uint4*)&hsm[OFF_B0 + fn * RB_BSR + fkh] = fv;
    __syncthreads();

    float accC[2][2][4];
#pragma unroll
    for (int mi = 0; mi < 2; mi++)
#pragma unroll
        for (int ni = 0; ni < 2; ni++)
#pragma unroll
            for (int q = 0; q < 4; q++) accC[mi][ni][q] = 0.f;

    unsigned cAddrBase = ((wn * 16 + (jsel >> 1) * 8 + jrow) * RB_BSR + (jsel & 1) * 8) * 2;

    for (int kt = 0; kt < 8; kt++) {
        int cur = kt & 1;
        if (kt + 1 < 8 && tid < 128)
            fv = *(const uint4*)&fcw16[((kt + 1) * 64 + fn) * 16 + fkh];
        {
            unsigned af[2][4], bf[2][2];
            unsigned hA = sbh + OFF_HS * 2 + hAddrBase + kt * 16 * 2;
            unsigned bA = sbh + (OFF_B0 + cur * (128 * RB_BSR)) * 2 + cAddrBase;
#pragma unroll
            for (int mi = 0; mi < 2; mi++)
                LDSM_X4(af[mi][0], af[mi][1], af[mi][2], af[mi][3],
                        hA + mi * (16 * RB_HSR) * 2);
            LDSM_X4(bf[0][0], bf[0][1], bf[1][0], bf[1][1], bA);
#pragma unroll
            for (int mi = 0; mi < 2; mi++)
#pragma unroll
                for (int ni = 0; ni < 2; ni++)
                    MMA_F16(accC[mi][ni], af[mi], bf[ni]);
        }
        if (kt + 1 < 8) {
            if (tid < 128)
                *(uint4*)&hsm[OFF_B0 + (cur ^ 1) * (128 * RB_BSR) + fn * RB_BSR + fkh] = fv;
        }
        __syncthreads();
    }

    // ---- epilogue C: g_c = accC + fcb ----
#pragma unroll
    for (int mi = 0; mi < 2; mi++)
#pragma unroll
        for (int ni = 0; ni < 2; ni++) {
            int n = wn * 16 + ni * 8 + lc * 2;
            float bv0 = fcb[n], bv1 = fcb[n + 1];
#pragma unroll
            for (int half = 0; half < 2; half++) {
                int m = bm + wm * 32 + mi * 16 + lr + half * 8;
                *(float2*)&Cout[(size_t)m * CDIM + n] =
                    make_float2(accC[mi][ni][half * 2 + 0] + bv0,
                                accC[mi][ni][half * 2 + 1] + bv1);
            }
        }
}

// ---------------- pooling (fp16 gather, hmax2) ----------------
__global__ void k_poolmax8() {
    int t = blockIdx.x * 256 + threadIdx.x;   // 3*NSEG*16
    int f8 = t & 15;
    int bin = (t >> 4) & (NSEG - 1);
    int pl = t >> 20;
    int cnt = g_bcnt[pl][bin];
    if (cnt == 0) return;
    int off = g_boff[pl][bin] + g_bsum[pl][bin >> 11];
    __half2 mneg = __floats2half2_rn(-65504.f, -65504.f);
    __half2 m0 = mneg, m1 = mneg, m2 = mneg, m3 = mneg;
    for (int j = 0; j < cnt; j++) {
        int pt = g_pts[pl][off + j];
        uint4 v = *(const uint4*)&g_net[(size_t)pt * H + f8 * 8];
        m0 = __hmax2(m0, *(__half2*)&v.x);
        m1 = __hmax2(m1, *(__half2*)&v.y);
        m2 = __hmax2(m2, *(__half2*)&v.z);
        m3 = __hmax2(m3, *(__half2*)&v.w);
    }
    uint4 o;
    o.x = *(unsigned*)&m0; o.y = *(unsigned*)&m1;
    o.z = *(unsigned*)&m2; o.w = *(unsigned*)&m3;
    *(uint4*)&g_segmax[pl][(size_t)bin * H + f8 * 8] = o;
}

// ---------------- fused mean + transposed output ----------------
__global__ void __launch_bounds__(256)
k_meanout(float* __restrict__ out) {
    __shared__ float smean[32][72];
    int pix0 = blockIdx.x * 32;
    int pb = blockIdx.y;
    int pl = pb >> 2, b = pb & 3;
    int t = threadIdx.x;

    int binl = t >> 3;
    int c8 = (t & 7) * 8;
    int bin = b * R2_ + pix0 + binl;
    int cnt = g_bcnt[pl][bin];
    float4 s0 = make_float4(0.f, 0.f, 0.f, 0.f);
    float4 s1 = make_float4(0.f, 0.f, 0.f, 0.f);
    if (cnt > 0) {
        int off = g_boff[pl][bin] + g_bsum[pl][bin >> 11];
        for (int j = 0; j < cnt; j++) {
            int pt = g_pts[pl][off + j];
            float4 v0 = *(const float4*)&g_c[(size_t)pt * CDIM + c8];
            float4 v1 = *(const float4*)&g_c[(size_t)pt * CDIM + c8 + 4];
            s0.x += v0.x; s0.y += v0.y; s0.z += v0.z; s0.w += v0.w;
            s1.x += v1.x; s1.y += v1.y; s1.z += v1.z; s1.w += v1.w;
        }
        float inv = 1.0f / (float)cnt;
        s0.x *= inv; s0.y *= inv; s0.z *= inv; s0.w *= inv;
        s1.x *= inv; s1.y *= inv; s1.z *= inv; s1.w *= inv;
    }
    *(float4*)&smean[binl][c8] = s0;
    *(float4*)&smean[binl][c8 + 4] = s1;
    __syncthreads();

    int tx = t & 31;
    int ty = t >> 5;
#pragma unroll
    for (int k = 0; k < 8; k++) {
        int ch = ty * 8 + k;
        out[((size_t)pb * CDIM + ch) * R2_ + pix0 + tx] = smean[tx][ch];
    }
}

// ---------------- launcher ----------------
extern "C" void kernel_launch(void* const* d_in, const int* in_sizes, int n_in,
                              void* d_out, int out_size) {
    const float* p   = (const float*)d_in[0];
    const float* fw  = (const float*)d_in[1];
    const float* fb  = (const float*)d_in[2];
    const float* w0  = (const float*)d_in[3];
    const float* b0  = (const float*)d_in[4];
    const float* w1  = (const float*)d_in[5];
    const float* b1  = (const float*)d_in[6];
    const float* ws  = (const float*)d_in[7];
    const float* fcw = (const float*)d_in[8];
    const float* fcb = (const float*)d_in[9];
    float* out = (float*)d_out;

    __half *gn, *gw;
    float* gc;
    cudaGetSymbolAddress((void**)&gn, g_net);
    cudaGetSymbolAddress((void**)&gc, g_c);
    cudaGetSymbolAddress((void**)&gw, g_wcvt);

    static bool attr_done = false;
    if (!attr_done) {
        cudaFuncSetAttribute(k_resblock<0, 0>,
                             cudaFuncAttributeMaxDynamicSharedMemorySize, RB_SMEM_BYTES);
        cudaFuncSetAttribute(k_resblock<1, 0>,
                             cudaFuncAttributeMaxDynamicSharedMemorySize, RB_SMEM_BYTES);
        cudaFuncSetAttribute(k_resblock<1, 1>,
                             cudaFuncAttributeMaxDynamicSharedMemorySize, RB_SMEM_BYTES);
        attr_done = true;
    }

    k_cvtw<<<(NB * WBLK + 8192) / 256, 256>>>(w0, ws, w1, fcw);  // + bcnt zero
    k_idxcount<<<BT / 256, 256>>>(p);
    k_scanA<<<dim3(32, 3), 1024>>>();
    k_resblock<0, 0><<<BT / 64, 256, RB_SMEM_BYTES>>>(
        p, fw, fb, gw, b0, gw + 65536, b1, gw + 32768, gn,
        nullptr, nullptr, nullptr);                              // 4th launch
    k_scanB<<<1, 96>>>();
    k_scatter<<<BT / 256, 256>>>();

    for (int i = 1; i < NB; i++) {
        k_poolmax8<<<(3 * NSEG * 16) / 256, 256>>>();
        const __half* wb = gw + (size_t)i * WBLK;
        if (i < NB - 1) {
            k_resblock<1, 0><<<BT / 64, 256, RB_SMEM_BYTES>>>(
                nullptr, nullptr, nullptr,
                wb, b0 + (size_t)i * H,
                wb + 65536, b1 + (size_t)i * H,
                wb + 32768, gn,
                nullptr, nullptr, nullptr);
        } else {
            k_resblock<1, 1><<<BT / 64, 256, RB_SMEM_BYTES>>>(
                nullptr, nullptr, nullptr,
                wb, b0 + (size_t)i * H,
                wb + 65536, b1 + (size_t)i * H,
                wb + 32768, gn,
                gw + FCW_OFF, fcb, gc);
        }
    }

    k_meanout<<<dim3(R2_ / 32, 3 * B_), 256>>>(out);
}

// round 17
// speedup vs baseline: 1.3305x; 1.3305x over previous
#include <cuda_runtime.h>
#include <cuda_fp16.h>
#include <stdint.h>
#include <float.h>
#include <math.h>

// ---------------- problem constants ----------------
#define B_    4
#define T_    32768
#define BT    (B_ * T_)          // 131072 points
#define RESO_ 128
#define R2_   (RESO_ * RESO_)    // 16384
#define NSEG  (B_ * R2_)         // 65536 segments
#define H     128
#define H2    256
#define CDIM  64
#define NB    5

// per-block converted-weight region (halves): w0 (32768) | ws (32768) | w1 (16384)
#define WBLK  81920
#define FCW_OFF (NB * WBLK)      // fc_c weight, tiled fp16 [8 tiles][64][16] = 8192

// ---------------- scratch (device globals, no allocation) ----------------
__device__ int    g_idx[3][BT];
__device__ int    g_rank[3][BT];
__device__ int    g_bcnt[3][NSEG];
__device__ int    g_boff[3][NSEG];        // chunk-local exclusive offsets
__device__ int    g_bsum[3][32];          // exclusive chunk base offsets
__device__ int    g_pts[3][BT];
__device__ __align__(16) __half g_net[(size_t)BT * H];
__device__ __align__(16) __half g_segmax[3][(size_t)NSEG * H];
__device__ __align__(16) __half g_wcvt[NB * WBLK + 8192];
__device__ float  g_c[(size_t)BT * CDIM];

// ---------------- helpers ----------------
__device__ __forceinline__ int norm_bin(float v) {
    float u = v / 1.10001f + 0.5f;
    u = fminf(fmaxf(u, 0.0f), 0.99999f);
    int q = (int)(u * 128.0f);
    return q < 127 ? q : 127;
}

__device__ __forceinline__ uint32_t smem_u32(const void* p) {
    uint32_t a;
    asm("{ .reg .u64 t; cvta.to.shared.u64 t, %1; cvt.u32.u64 %0, t; }"
        : "=r"(a) : "l"(p));
    return a;
}

#define LDSM_X4(r0, r1, r2, r3, addr) \
    asm volatile("ldmatrix.sync.aligned.m8n8.x4.shared.b16 {%0,%1,%2,%3}, [%4];" \
        : "=r"(r0), "=r"(r1), "=r"(r2), "=r"(r3) : "r"(addr))

// ---------------- weight convert (+ bcnt zero) ----------------
// W[K][128] fp32 -> fp16 tiled: elem (k,n) at ((k>>4)*128 + n)*16 + (k&15)
// fcw[K=128][64] -> tiled ((k>>4)*64 + n)*16 + (k&15) at FCW_OFF
__global__ void k_cvtw(const float* __restrict__ w0,
                       const float* __restrict__ ws,
                       const float* __restrict__ w1,
                       const float* __restrict__ fcw) {
    int t = blockIdx.x * 256 + threadIdx.x;        // 0 .. NB*WBLK+8192-1
    if (t < 3 * NSEG) (&g_bcnt[0][0])[t] = 0;      // fused zeroing
    if (t >= NB * WBLK) {
        int r = t - NB * WBLK;                     // < 8192
        int k = r >> 6, n = r & 63;
        g_wcvt[FCW_OFF + ((k >> 4) * 64 + n) * 16 + (k & 15)] =
            __float2half(fcw[r]);
        return;
    }
    int blk = t / WBLK;
    int r = t - blk * WBLK;
    const float* src;
    int base;
    if (r < 32768)      { src = w0 + (size_t)blk * 32768 + r;           base = 0;     }
    else if (r < 65536) { src = ws + (size_t)blk * 32768 + (r - 32768); base = 32768; r -= 32768; }
    else                { src = w1 + (size_t)blk * 16384 + (r - 65536); base = 65536; r -= 65536; }
    int k = r >> 7, n = r & 127;
    g_wcvt[(size_t)blk * WBLK + base + ((k >> 4) * 128 + n) * 16 + (k & 15)] =
        __float2half(*src);
}

// ---------------- index / CSR build ----------------
__global__ void k_idxcount(const float* __restrict__ p) {
    int i = blockIdx.x * 256 + threadIdx.x;
    if (i >= BT) return;
    float x = p[3 * i + 0], y = p[3 * i + 1], z = p[3 * i + 2];
    int base = (i / T_) * R2_;
    int ix = norm_bin(x), iy = norm_bin(y), iz = norm_bin(z);
    int idx0 = base + ix + RESO_ * iz;
    int idx1 = base + ix + RESO_ * iy;
    int idx2 = base + iy + RESO_ * iz;
    g_idx[0][i] = idx0; g_idx[1][i] = idx1; g_idx[2][i] = idx2;
    g_rank[0][i] = atomicAdd(&g_bcnt[0][idx0], 1);
    g_rank[1][i] = atomicAdd(&g_bcnt[1][idx1], 1);
    g_rank[2][i] = atomicAdd(&g_bcnt[2][idx2], 1);
}

__global__ void k_scanA() {       // 2048-elem chunks, 32 chunks/plane
    int pl = blockIdx.y, chunk = blockIdx.x;
    int tid = threadIdx.x;
    int base = chunk * 2048 + tid * 2;
    int v0 = g_bcnt[pl][base], v1 = g_bcnt[pl][base + 1];
    int v = v0 + v1;
    int lane = tid & 31, wid = tid >> 5;
    int x = v;
#pragma unroll
    for (int o = 1; o < 32; o <<= 1) {
        int y = __shfl_up_sync(0xffffffffu, x, o);
        if (lane >= o) x += y;
    }
    __shared__ int wsum[32];
    if (lane == 31) wsum[wid] = x;
    __syncthreads();
    if (wid == 0) {
        int s = wsum[lane];
#pragma unroll
        for (int o = 1; o < 32; o <<= 1) {
            int y = __shfl_up_sync(0xffffffffu, s, o);
            if (lane >= o) s += y;
        }
        wsum[lane] = s;
    }
    __syncthreads();
    int incl = x + (wid ? wsum[wid - 1] : 0);
    int excl = incl - v;
    g_boff[pl][base] = excl;
    g_boff[pl][base + 1] = excl + v0;
    if (tid == 1023) g_bsum[pl][chunk] = incl;
}

__global__ void k_scanB() {       // 1 block, 96 threads: warp per plane
    int pl = threadIdx.x >> 5, lane = threadIdx.x & 31;
    int v = g_bsum[pl][lane];
    int x = v;
#pragma unroll
    for (int o = 1; o < 32; o <<= 1) {
        int y = __shfl_up_sync(0xffffffffu, x, o);
        if (lane >= o) x += y;
    }
    g_bsum[pl][lane] = x - v;     // exclusive chunk base
}

__global__ void k_scatter() {
    int i = blockIdx.x * 256 + threadIdx.x;   // BT
#pragma unroll
    for (int pl = 0; pl < 3; pl++) {
        int bin = g_idx[pl][i];
        int off = g_boff[pl][bin] + g_bsum[pl][bin >> 11];
        g_pts[pl][off + g_rank[pl][i]] = i;
    }
}

// ---------------- fused resblock (fp16 MMA + ldmatrix, 4-deep ring) -------
// MODE 0: X = fc_pos(p) inline.  MODE 1: X = [net | sum3 segmax(idx)] inline.
// NET = X@ws + relu(relu(X)@w0 + b0)@w1 + b1;  FC 1: also C = net@fcw + fcb.
// BM=64, 256 thr (wm 2 x wn 4), warp tile 32x32, 2 CTAs/SM.
// LDG+STS staging (L1-cached weights), 2 k-tiles per __syncthreads.
// smem (halves):
//   AS  [4][64][24]   @0
//   B0  [4][128][24]  @6144
//   BS  [4][128][24]  @18432
//   HS  [64][136]     @30720
#define RB_ASR 24
#define RB_BSR 24
#define RB_HSR 136
#define OFF_B0 6144
#define OFF_BS 18432
#define OFF_HS 30720
#define RB_SMEM_BYTES ((30720 + 64 * RB_HSR) * 2)   // 78848 B

#define MMA_F16(d, a, b) \
    asm volatile( \
        "mma.sync.aligned.m16n8k16.row.col.f32.f16.f16.f32 " \
        "{%0,%1,%2,%3}, {%4,%5,%6,%7}, {%8,%9}, {%0,%1,%2,%3};" \
        : "+f"((d)[0]), "+f"((d)[1]), "+f"((d)[2]), "+f"((d)[3]) \
        : "r"((a)[0]), "r"((a)[1]), "r"((a)[2]), "r"((a)[3]), \
          "r"((b)[0]), "r"((b)[1]))

template <int MODE, int FC>
__global__ void __launch_bounds__(256, 2)
k_resblock(const float* __restrict__ P,      // MODE 0: [BT,3]
           const float* __restrict__ FW,     // MODE 0: [3,256]
           const float* __restrict__ FB,     // MODE 0: [256]
           const __half* __restrict__ w0h,   // tiled fp16 [16 tiles][128][16]
           const float* __restrict__ b0,
           const __half* __restrict__ w1h,   // tiled fp16 [8 tiles][128][16]
           const float* __restrict__ b1,
           const __half* __restrict__ wsh,   // tiled fp16 [16 tiles][128][16]
           __half* __restrict__ NET,         // [BT,128] fp16 (in-place safe)
           const __half* __restrict__ fcw16, // FC: tiled fp16 [8 tiles][64][16]
           const float* __restrict__ fcb,    // FC: [64]
           float* __restrict__ Cout) {       // FC: [BT,64]
    extern __shared__ __half hsm[];
    uint32_t sbh = smem_u32(hsm);
    int tid = threadIdx.x;
    int bm = blockIdx.x * 64;
    int w = tid >> 5, lane = tid & 31;
    int wm = w & 1, wn = w >> 1;              // 2 x 4
    int lr = lane >> 2, lc = lane & 3;
    int jrow = lane & 7, jsel = lane >> 3;    // ldmatrix lane mapping

    int arow = tid >> 2;            // 0..63
    int acol = (tid & 3) * 4;       // 0,4,8,12
    int bn = tid & 127;             // n for B staging
    int bkh = (tid >> 7) * 8;       // k-half offset (0 or 8)

    // per-row state for A synthesis
    int row = bm + arow;
    float p0, p1, p2;
    int ix0, ix1, ix2;
    if (MODE == 0) {
        p0 = P[3 * row]; p1 = P[3 * row + 1]; p2 = P[3 * row + 2];
    } else {
        ix0 = g_idx[0][row]; ix1 = g_idx[1][row]; ix2 = g_idx[2][row];
    }

    float accH[2][4][4];
    float accS[2][4][4];
#pragma unroll
    for (int mi = 0; mi < 2; mi++)
#pragma unroll
        for (int ni = 0; ni < 4; ni++)
#pragma unroll
            for (int q = 0; q < 4; q++) { accH[mi][ni][q] = 0.f; accS[mi][ni][q] = 0.f; }

    uint2 ar;
    uint4 b0v, bsv;      // weight prefetch registers

    auto loadA = [&](int k0) -> uint2 {
        int col = k0 + acol;
        if (MODE == 0) {
            float4 wa = *(const float4*)&FW[col];
            float4 wb = *(const float4*)&FW[H2 + col];
            float4 wc = *(const float4*)&FW[2 * H2 + col];
            float4 bb = *(const float4*)&FB[col];
            __half2 h0 = __floats2half2_rn(p0 * wa.x + p1 * wb.x + p2 * wc.x + bb.x,
                                           p0 * wa.y + p1 * wb.y + p2 * wc.y + bb.y);
            __half2 h1 = __floats2half2_rn(p0 * wa.z + p1 * wb.z + p2 * wc.z + bb.z,
                                           p0 * wa.w + p1 * wb.w + p2 * wc.w + bb.w);
            uint2 r; r.x = *(unsigned*)&h0; r.y = *(unsigned*)&h1;
            return r;
        } else {
            if (col < H) {   // uniform per k-tile
                return *(const uint2*)&g_net[(size_t)row * H + col];
            } else {
                int c2 = col - H;
                uint2 ua = *(const uint2*)&g_segmax[0][(size_t)ix0 * H + c2];
                uint2 ub = *(const uint2*)&g_segmax[1][(size_t)ix1 * H + c2];
                uint2 uc = *(const uint2*)&g_segmax[2][(size_t)ix2 * H + c2];
                float2 a0 = __half22float2(*(__half2*)&ua.x), a1 = __half22float2(*(__half2*)&ua.y);
                float2 e0 = __half22float2(*(__half2*)&ub.x), e1 = __half22float2(*(__half2*)&ub.y);
                float2 c0 = __half22float2(*(__half2*)&uc.x), c1 = __half22float2(*(__half2*)&uc.y);
                __half2 h0 = __floats2half2_rn(a0.x + e0.x + c0.x, a0.y + e0.y + c0.y);
                __half2 h1 = __floats2half2_rn(a1.x + e1.x + c1.x, a1.y + e1.y + c1.y);
                uint2 r; r.x = *(unsigned*)&h0; r.y = *(unsigned*)&h1;
                return r;
            }
        }
    };

    auto stA = [&](int buf, uint2 v) {
        *(uint2*)&hsm[buf * (64 * RB_ASR) + arow * RB_ASR + acol] = v;
    };
    auto ldW = [&](const __half* W16, int kt) -> uint4 {
        return *(const uint4*)&W16[((size_t)kt * 128 + bn) * 16 + bkh];
    };
    auto stB = [&](int offb, int buf, uint4 v) {
        *(uint4*)&hsm[offb + buf * (128 * RB_BSR) + bn * RB_BSR + bkh] = v;
    };

    __half2 zero2 = __floats2half2_rn(0.f, 0.f);
    unsigned zu = *(unsigned*)&zero2;

    unsigned aAddrBase = ((wm * 32 + (jsel & 1) * 8 + jrow) * RB_ASR + (jsel >> 1) * 8) * 2;
    unsigned bAddrBase = ((wn * 32 + (jsel >> 1) * 8 + jrow) * RB_BSR + (jsel & 1) * 8) * 2;
    unsigned hAddrBase = ((wm * 32 + (jsel & 1) * 8 + jrow) * RB_HSR + (jsel >> 1) * 8) * 2;

    auto computeP1 = [&](int kt) {
        int cur = kt & 3;
        unsigned afr[2][4], afh[2][4], bf0[4][2], bfs[4][2];
        unsigned aA = sbh + cur * (64 * RB_ASR) * 2 + aAddrBase;
        unsigned bA = sbh + (OFF_B0 + cur * (128 * RB_BSR)) * 2 + bAddrBase;
        unsigned sA = sbh + (OFF_BS + cur * (128 * RB_BSR)) * 2 + bAddrBase;
#pragma unroll
        for (int mi = 0; mi < 2; mi++) {
            LDSM_X4(afr[mi][0], afr[mi][1], afr[mi][2], afr[mi][3],
                    aA + mi * (16 * RB_ASR) * 2);
#pragma unroll
            for (int q = 0; q < 4; q++) {
                __half2 hh = __hmax2(*(__half2*)&afr[mi][q], *(__half2*)&zu);
                afh[mi][q] = *(unsigned*)&hh;
            }
        }
        LDSM_X4(bf0[0][0], bf0[0][1], bf0[1][0], bf0[1][1], bA);
        LDSM_X4(bf0[2][0], bf0[2][1], bf0[3][0], bf0[3][1], bA + (16 * RB_BSR) * 2);
        LDSM_X4(bfs[0][0], bfs[0][1], bfs[1][0], bfs[1][1], sA);
        LDSM_X4(bfs[2][0], bfs[2][1], bfs[3][0], bfs[3][1], sA + (16 * RB_BSR) * 2);
#pragma unroll
        for (int mi = 0; mi < 2; mi++)
#pragma unroll
            for (int ni = 0; ni < 4; ni++) {
                MMA_F16(accH[mi][ni], afh[mi], bf0[ni]);
                MMA_F16(accS[mi][ni], afr[mi], bfs[ni]);
            }
    };

    // ---- phase 1: K=256, 2 k-tiles per barrier ----
    ar = loadA(0);  b0v = ldW(w0h, 0); bsv = ldW(wsh, 0);
    stA(0, ar); stB(OFF_B0, 0, b0v); stB(OFF_BS, 0, bsv);
    ar = loadA(16); b0v = ldW(w0h, 1); bsv = ldW(wsh, 1);
    stA(1, ar); stB(OFF_B0, 1, b0v); stB(OFF_BS, 1, bsv);
    ar = loadA(32); b0v = ldW(w0h, 2); bsv = ldW(wsh, 2);
    __syncthreads();

    for (int s = 0; s < 16; s += 2) {
        computeP1(s);
        if (s + 2 < 16) {
            stA((s + 2) & 3, ar);
            stB(OFF_B0, (s + 2) & 3, b0v);
            stB(OFF_BS, (s + 2) & 3, bsv);
        }
        if (s + 3 < 16) {
            ar = loadA((s + 3) * 16); b0v = ldW(w0h, s + 3); bsv = ldW(wsh, s + 3);
        }
        computeP1(s + 1);
        if (s + 3 < 16) {
            stA((s + 3) & 3, ar);
            stB(OFF_B0, (s + 3) & 3, b0v);
            stB(OFF_BS, (s + 3) & 3, bsv);
        }
        if (s + 4 < 16) {
            ar = loadA((s + 4) * 16); b0v = ldW(w0h, s + 4); bsv = ldW(wsh, s + 4);
        }
        __syncthreads();
    }

    // ---- store HS = relu(accH + b0); prefetch w1 tiles 0,1 ----
    b0v = ldW(w1h, 0); bsv = ldW(w1h, 1);
#pragma unroll
    for (int mi = 0; mi < 2; mi++)
#pragma unroll
        for (int ni = 0; ni < 4; ni++) {
            int n = wn * 32 + ni * 8 + lc * 2;
            float bv0 = b0[n], bv1 = b0[n + 1];
#pragma unroll
            for (int half = 0; half < 2; half++) {
                int m = wm * 32 + mi * 16 + lr + half * 8;
                __half2 hv = __floats2half2_rn(
                    fmaxf(accH[mi][ni][half * 2 + 0] + bv0, 0.f),
                    fmaxf(accH[mi][ni][half * 2 + 1] + bv1, 0.f));
                *(__half2*)&hsm[OFF_HS + m * RB_HSR + n] = hv;
            }
        }
    __syncthreads();   // HS visible; all phase-1 B0 bufs dead
    stB(OFF_B0, 0, b0v);
    stB(OFF_B0, 1, bsv);
    b0v = ldW(w1h, 2);
    __syncthreads();

    auto computeP2 = [&](int kt) {
        int cur = kt & 3;
        unsigned af[2][4], bf[4][2];
        unsigned hA = sbh + OFF_HS * 2 + hAddrBase + kt * 16 * 2;
        unsigned bA = sbh + (OFF_B0 + cur * (128 * RB_BSR)) * 2 + bAddrBase;
#pragma unroll
        for (int mi = 0; mi < 2; mi++)
            LDSM_X4(af[mi][0], af[mi][1], af[mi][2], af[mi][3],
                    hA + mi * (16 * RB_HSR) * 2);
        LDSM_X4(bf[0][0], bf[0][1], bf[1][0], bf[1][1], bA);
        LDSM_X4(bf[2][0], bf[2][1], bf[3][0], bf[3][1], bA + (16 * RB_BSR) * 2);
#pragma unroll
        for (int mi = 0; mi < 2; mi++)
#pragma unroll
            for (int ni = 0; ni < 4; ni++)
                MMA_F16(accS[mi][ni], af[mi], bf[ni]);
    };

    // ---- phase 2: accS += relu(hidden) @ w1, K=128 ----
    for (int s = 0; s < 8; s += 2) {
        computeP2(s);
        if (s + 2 < 8) stB(OFF_B0, (s + 2) & 3, b0v);
        if (s + 3 < 8) b0v = ldW(w1h, s + 3);
        computeP2(s + 1);
        if (s + 3 < 8) stB(OFF_B0, (s + 3) & 3, b0v);
        if (s + 4 < 8) b0v = ldW(w1h, s + 4);
        __syncthreads();
    }

    // ---- epilogue: net = accS + b1 ----
    if (!FC) {
#pragma unroll
        for (int mi = 0; mi < 2; mi++)
#pragma unroll
            for (int ni = 0; ni < 4; ni++) {
                int n = wn * 32 + ni * 8 + lc * 2;
                float bv0 = b1[n], bv1 = b1[n + 1];
#pragma unroll
                for (int half = 0; half < 2; half++) {
                    int m = bm + wm * 32 + mi * 16 + lr + half * 8;
                    *(__half2*)&NET[(size_t)m * H + n] =
                        __floats2half2_rn(accS[mi][ni][half * 2 + 0] + bv0,
                                          accS[mi][ni][half * 2 + 1] + bv1);
                }
            }
        return;
    }

    // ---- FC path: net -> HS (fp16), then C = net@fcw + fcb ----
#pragma unroll
    for (int mi = 0; mi < 2; mi++)
#pragma unroll
        for (int ni = 0; ni < 4; ni++) {
            int n = wn * 32 + ni * 8 + lc * 2;
            float bv0 = b1[n], bv1 = b1[n + 1];
#pragma unroll
            for (int half = 0; half < 2; half++) {
                int m = wm * 32 + mi * 16 + lr + half * 8;
                *(__half2*)&hsm[OFF_HS + m * RB_HSR + n] =
                    __floats2half2_rn(accS[mi][ni][half * 2 + 0] + bv0,
                                      accS[mi][ni][half * 2 + 1] + bv1);
            }
        }
    int fn = tid & 63, fkh = ((tid >> 6) & 1) * 8;
    uint4 fv;
    if (tid < 128) {
        fv = *(const uint4*)&fcw16[(0 * 64 + fn) * 16 + fkh];
    }
    __syncthreads();   // HS(net) visible; phase-2 B0 dead
    if (tid < 128)
        *(uint4*)&hsm[OFF_B0 + fn * RB_BSR + fkh] = fv;
    __syncthreads();

    float accC[2][2][4];
#pragma unroll
    for (int mi = 0; mi < 2; mi++)
#pragma unroll
        for (int ni = 0; ni < 2; ni++)
#pragma unroll
            for (int q = 0; q < 4; q++) accC[mi][ni][q] = 0.f;

    unsigned cAddrBase = ((wn * 16 + (jsel >> 1) * 8 + jrow) * RB_BSR + (jsel & 1) * 8) * 2;

    for (int kt = 0; kt < 8; kt++) {
        int cur = kt & 1;
        if (kt + 1 < 8 && tid < 128)
            fv = *(const uint4*)&fcw16[((kt + 1) * 64 + fn) * 16 + fkh];
        {
            unsigned af[2][4], bf[2][2];
            unsigned hA = sbh + OFF_HS * 2 + hAddrBase + kt * 16 * 2;
            unsigned bA = sbh + (OFF_B0 + cur * (128 * RB_BSR)) * 2 + cAddrBase;
#pragma unroll
            for (int mi = 0; mi < 2; mi++)
                LDSM_X4(af[mi][0], af[mi][1], af[mi][2], af[mi][3],
                        hA + mi * (16 * RB_HSR) * 2);
            LDSM_X4(bf[0][0], bf[0][1], bf[1][0], bf[1][1], bA);
#pragma unroll
            for (int mi = 0; mi < 2; mi++)
#pragma unroll
                for (int ni = 0; ni < 2; ni++)
                    MMA_F16(accC[mi][ni], af[mi], bf[ni]);
        }
        if (kt + 1 < 8) {
            if (tid < 128)
                *(uint4*)&hsm[OFF_B0 + (cur ^ 1) * (128 * RB_BSR) + fn * RB_BSR + fkh] = fv;
        }
        __syncthreads();
    }

    // ---- epilogue C: g_c = accC + fcb ----
#pragma unroll
    for (int mi = 0; mi < 2; mi++)
#pragma unroll
        for (int ni = 0; ni < 2; ni++) {
            int n = wn * 16 + ni * 8 + lc * 2;
            float bv0 = fcb[n], bv1 = fcb[n + 1];
#pragma unroll
            for (int half = 0; half < 2; half++) {
                int m = bm + wm * 32 + mi * 16 + lr + half * 8;
                *(float2*)&Cout[(size_t)m * CDIM + n] =
                    make_float2(accC[mi][ni][half * 2 + 0] + bv0,
                                accC[mi][ni][half * 2 + 1] + bv1);
            }
        }
}

// ---------------- pooling (fp16 gather, hmax2) ----------------
__global__ void k_poolmax8() {
    int t = blockIdx.x * 256 + threadIdx.x;   // 3*NSEG*16
    int f8 = t & 15;
    int bin = (t >> 4) & (NSEG - 1);
    int pl = t >> 20;
    int cnt = g_bcnt[pl][bin];
    if (cnt == 0) return;
    int off = g_boff[pl][bin] + g_bsum[pl][bin >> 11];
    __half2 mneg = __floats2half2_rn(-65504.f, -65504.f);
    __half2 m0 = mneg, m1 = mneg, m2 = mneg, m3 = mneg;
    for (int j = 0; j < cnt; j++) {
        int pt = g_pts[pl][off + j];
        uint4 v = *(const uint4*)&g_net[(size_t)pt * H + f8 * 8];
        m0 = __hmax2(m0, *(__half2*)&v.x);
        m1 = __hmax2(m1, *(__half2*)&v.y);
        m2 = __hmax2(m2, *(__half2*)&v.z);
        m3 = __hmax2(m3, *(__half2*)&v.w);
    }
    uint4 o;
    o.x = *(unsigned*)&m0; o.y = *(unsigned*)&m1;
    o.z = *(unsigned*)&m2; o.w = *(unsigned*)&m3;
    *(uint4*)&g_segmax[pl][(size_t)bin * H + f8 * 8] = o;
}

// ---------------- fused mean + transposed output ----------------
__global__ void __launch_bounds__(256)
k_meanout(float* __restrict__ out) {
    __shared__ float smean[32][72];
    int pix0 = blockIdx.x * 32;
    int pb = blockIdx.y;
    int pl = pb >> 2, b = pb & 3;
    int t = threadIdx.x;

    int binl = t >> 3;
    int c8 = (t & 7) * 8;
    int bin = b * R2_ + pix0 + binl;
    int cnt = g_bcnt[pl][bin];
    float4 s0 = make_float4(0.f, 0.f, 0.f, 0.f);
    float4 s1 = make_float4(0.f, 0.f, 0.f, 0.f);
    if (cnt > 0) {
        int off = g_boff[pl][bin] + g_bsum[pl][bin >> 11];
        for (int j = 0; j < cnt; j++) {
            int pt = g_pts[pl][off + j];
            float4 v0 = *(const float4*)&g_c[(size_t)pt * CDIM + c8];
            float4 v1 = *(const float4*)&g_c[(size_t)pt * CDIM + c8 + 4];
            s0.x += v0.x; s0.y += v0.y; s0.z += v0.z; s0.w += v0.w;
            s1.x += v1.x; s1.y += v1.y; s1.z += v1.z; s1.w += v1.w;
        }
        float inv = 1.0f / (float)cnt;
        s0.x *= inv; s0.y *= inv; s0.z *= inv; s0.w *= inv;
        s1.x *= inv; s1.y *= inv; s1.z *= inv; s1.w *= inv;
    }
    *(float4*)&smean[binl][c8] = s0;
    *(float4*)&smean[binl][c8 + 4] = s1;
    __syncthreads();

    int tx = t & 31;
    int ty = t >> 5;
#pragma unroll
    for (int k = 0; k < 8; k++) {
        int ch = ty * 8 + k;
        out[((size_t)pb * CDIM + ch) * R2_ + pix0 + tx] = smean[tx][ch];
    }
}

// ---------------- launcher ----------------
extern "C" void kernel_launch(void* const* d_in, const int* in_sizes, int n_in,
                              void* d_out, int out_size) {
    const float* p   = (const float*)d_in[0];
    const float* fw  = (const float*)d_in[1];
    const float* fb  = (const float*)d_in[2];
    const float* w0  = (const float*)d_in[3];
    const float* b0  = (const float*)d_in[4];
    const float* w1  = (const float*)d_in[5];
    const float* b1  = (const float*)d_in[6];
    const float* ws  = (const float*)d_in[7];
    const float* fcw = (const float*)d_in[8];
    const float* fcb = (const float*)d_in[9];
    float* out = (float*)d_out;

    __half *gn, *gw;
    float* gc;
    cudaGetSymbolAddress((void**)&gn, g_net);
    cudaGetSymbolAddress((void**)&gc, g_c);
    cudaGetSymbolAddress((void**)&gw, g_wcvt);

    static bool attr_done = false;
    if (!attr_done) {
        cudaFuncSetAttribute(k_resblock<0, 0>,
                             cudaFuncAttributeMaxDynamicSharedMemorySize, RB_SMEM_BYTES);
        cudaFuncSetAttribute(k_resblock<1, 0>,
                             cudaFuncAttributeMaxDynamicSharedMemorySize, RB_SMEM_BYTES);
        cudaFuncSetAttribute(k_resblock<1, 1>,
                             cudaFuncAttributeMaxDynamicSharedMemorySize, RB_SMEM_BYTES);
        attr_done = true;
    }

    k_cvtw<<<(NB * WBLK + 8192) / 256, 256>>>(w0, ws, w1, fcw);  // + bcnt zero
    k_idxcount<<<BT / 256, 256>>>(p);
    k_scanA<<<dim3(32, 3), 1024>>>();
    k_resblock<0, 0><<<BT / 64, 256, RB_SMEM_BYTES>>>(
        p, fw, fb, gw, b0, gw + 65536, b1, gw + 32768, gn,
        nullptr, nullptr, nullptr);                              // 4th launch
    k_scanB<<<1, 96>>>();
    k_scatter<<<BT / 256, 256>>>();

    for (int i = 1; i < NB; i++) {
        k_poolmax8<<<(3 * NSEG * 16) / 256, 256>>>();
        const __half* wb = gw + (size_t)i * WBLK;
        if (i < NB - 1) {
            k_resblock<1, 0><<<BT / 64, 256, RB_SMEM_BYTES>>>(
                nullptr, nullptr, nullptr,
                wb, b0 + (size_t)i * H,
                wb + 65536, b1 + (size_t)i * H,
                wb + 32768, gn,
                nullptr, nullptr, nullptr);
        } else {
            k_resblock<1, 1><<<BT / 64, 256, RB_SMEM_BYTES>>>(
                nullptr, nullptr, nullptr,
                wb, b0 + (size_t)i * H,
                wb + 65536, b1 + (size_t)i * H,
                wb + 32768, gn,
                gw + FCW_OFF, fcb, gc);
        }
    }

    k_meanout<<<dim3(R2_ / 32, 3 * B_), 256>>>(out);
}